// round 13
// baseline (speedup 1.0000x reference)
#include <cuda_runtime.h>
#include <cstdint>

// FuzzyNeuron via mma.sync tf32 (3xTF32 logw, 1x tf32 z), fused kernel.
// R13: (a) MMA asm de-volatiled -> ptxas may software-pipeline across chunk
// boundaries (volatile ordering was pinning source order; suspected binder
// for the R8-R12 23-25us plateau with all pipes <30%);
// (b) f/bias folded into C-fragment inits (-16 FADD/chunk, shorter epilogue
// chain); (c) R12 fragment-packed B retained (7 LDS/chunk).

typedef unsigned int u32;

#define LOG2E 1.4426950408889634f
#define BLOCK 128
#define GRID 512
#define TILES 2        // 512 CTAs x 2 tiles x 128 rows = 131072

// fragment layouts (conflict-free strides)
#define FL(j, ks, tig, g) (((j) * 4 + (ks)) * 40 + (tig) * 10 + (g))   // float4
#define FZ(j, ks, tig, g) (((j) * 2 + (ks)) * 48 + (tig) * 12 + (g))   // float2

__device__ __forceinline__ u32 tf32_bits(float v) {
    u32 r; asm("cvt.rna.tf32.f32 %0, %1;" : "=r"(r) : "f"(v)); return r;
}
__device__ __forceinline__ float exp2_fast(float v) {
    float r; asm("ex2.approx.ftz.f32 %0, %1;" : "=f"(r) : "f"(v)); return r;
}
// NOT volatile: pure dataflow lets ptxas reorder/interleave/pipeline.
__device__ __forceinline__ void mma8(float* c, const u32* a, u32 b0, u32 b1) {
    asm("mma.sync.aligned.m16n8k8.row.col.f32.tf32.tf32.f32 "
        "{%0,%1,%2,%3}, {%4,%5,%6,%7}, {%8,%9}, {%0,%1,%2,%3};"
        : "+f"(c[0]), "+f"(c[1]), "+f"(c[2]), "+f"(c[3])
        : "r"(a[0]), "r"(a[1]), "r"(a[2]), "r"(a[3]), "r"(b0), "r"(b1));
}

// logw coefficient for rule n, k-index k (0..31)
__device__ __forceinline__ float coefL(const float* mu, const float* sigma, int n, int k) {
    if (k < 16) {
        float m = mu[n * 16 + k], s = sigma[n * 16 + k];
        return 2.0f * __fdividef(0.5f, s * s) * m * LOG2E;      // multiplies x
    } else {
        float s = sigma[n * 16 + (k - 16)];
        return -__fdividef(0.5f, s * s) * LOG2E;                // multiplies x^2
    }
}

__global__ void __launch_bounds__(BLOCK, 4)
fuzzy_mma_kernel(const float* __restrict__ x,
                 const float* __restrict__ mu,
                 const float* __restrict__ sigma,
                 const float* __restrict__ rho,
                 float* __restrict__ out) {
    __shared__ __align__(16) float4 sBl[8 * 4 * 40];   // fragment-packed logw B
    __shared__ __align__(8)  float2 sBz[8 * 2 * 48];   // fragment-packed z B
    __shared__ __align__(16) float2 sFB[64];           // {f*log2e, bias}

    const int tid = threadIdx.x;
    const int w = tid >> 5, lane = tid & 31;
    const int g = lane >> 2, tig = lane & 3;

    // ---- build fragment-packed B (once per CTA) ----
    for (int i = tid; i < 1024; i += BLOCK) {          // Bl: (j,ks,tig,g)
        int gg = i & 7, tt = (i >> 3) & 3, ks = (i >> 5) & 3, j = i >> 7;
        int n = j * 8 + gg, k0 = ks * 8 + tt;
        float b0 = coefL(mu, sigma, n, k0);
        float b1 = coefL(mu, sigma, n, k0 + 4);
        float b0h = __uint_as_float(tf32_bits(b0));
        float b1h = __uint_as_float(tf32_bits(b1));
        sBl[FL(j, ks, tt, gg)] = make_float4(b0h, b1h, b0 - b0h, b1 - b1h);
    }
    for (int i = tid; i < 512; i += BLOCK) {           // Bz: (j,ks,tig,g)
        int gg = i & 7, tt = (i >> 3) & 3, ks = (i >> 5) & 1, j = i >> 6;
        int n = j * 8 + gg, k0 = ks * 8 + tt;
        sBz[FZ(j, ks, tt, gg)] =
            make_float2(__uint_as_float(tf32_bits(rho[n * 17 + k0])),
                        __uint_as_float(tf32_bits(rho[n * 17 + k0 + 4])));
    }
    if (tid < 64) {
        float f = 0.0f;
        for (int a = 0; a < 16; a++) {
            float m = mu[tid * 16 + a], s = sigma[tid * 16 + a];
            f -= m * m * __fdividef(0.5f, s * s);
        }
        sFB[tid] = make_float2(f * LOG2E, rho[tid * 17 + 16]);
    }
    __syncthreads();

    for (int t = 0; t < TILES; t++) {
        const int rowBase = (blockIdx.x + t * GRID) * BLOCK + w * 32;

        // ---- A fragments: rows {g,g+8} of 2 m-tiles; k-cols tig+4e ----
        u32 ah[2][4][4], al[2][4][4];
#pragma unroll
        for (int mt = 0; mt < 2; mt++)
#pragma unroll
            for (int rh = 0; rh < 2; rh++) {
                const float* xr = x + (size_t)(rowBase + mt * 16 + rh * 8 + g) * 16 + tig;
#pragma unroll
                for (int e = 0; e < 4; e++) {
                    float v = xr[4 * e];
                    u32 vh = tf32_bits(v);
                    u32 vl = tf32_bits(v - __uint_as_float(vh));
                    float v2 = v * v;
                    u32 v2h = tf32_bits(v2);
                    u32 v2l = tf32_bits(v2 - __uint_as_float(v2h));
                    int ks = e >> 1;
                    int slot = (e & 1) * 2 + rh;
                    ah[mt][ks][slot] = vh;      al[mt][ks][slot] = vl;
                    ah[mt][2 + ks][slot] = v2h; al[mt][2 + ks][slot] = v2l;
                }
            }

        float num[2][2] = {{0.f, 0.f}, {0.f, 0.f}};
        float den[2][2] = {{0.f, 0.f}, {0.f, 0.f}};

        // ---- 8 rule chunks; f/bias preloaded into C fragments ----
        for (int j = 0; j < 8; j++) {
            float4 Bf[4];
            float2 Bzf[2];
#pragma unroll
            for (int ks = 0; ks < 4; ks++) Bf[ks] = sBl[FL(j, ks, tig, g)];
#pragma unroll
            for (int ks = 0; ks < 2; ks++) Bzf[ks] = sBz[FZ(j, ks, tig, g)];
            float4 q = *reinterpret_cast<const float4*>(&sFB[8 * j + 2 * tig]); // {f0,b0,f1,b1}

            // c1 seeded with f, cz with bias; c2/c3 zero.
            float c1[2][4] = {{q.x, q.z, q.x, q.z}, {q.x, q.z, q.x, q.z}};
            float c2[2][4] = {{0.f,0.f,0.f,0.f},{0.f,0.f,0.f,0.f}};
            float c3[2][4] = {{0.f,0.f,0.f,0.f},{0.f,0.f,0.f,0.f}};
            float cz[2][4] = {{q.y, q.w, q.y, q.w}, {q.y, q.w, q.y, q.w}};
#pragma unroll
            for (int ks = 0; ks < 4; ks++) {
                u32 bh0 = __float_as_uint(Bf[ks].x), bh1 = __float_as_uint(Bf[ks].y);
                u32 bl0 = __float_as_uint(Bf[ks].z), bl1 = __float_as_uint(Bf[ks].w);
#pragma unroll
                for (int mt = 0; mt < 2; mt++) {
                    mma8(c1[mt], ah[mt][ks], bh0, bh1);
                    mma8(c2[mt], al[mt][ks], bh0, bh1);
                    mma8(c3[mt], ah[mt][ks], bl0, bl1);
                }
            }
#pragma unroll
            for (int ks = 0; ks < 2; ks++) {
                u32 bz0 = __float_as_uint(Bzf[ks].x), bz1 = __float_as_uint(Bzf[ks].y);
#pragma unroll
                for (int mt = 0; mt < 2; mt++)
                    mma8(cz[mt], ah[mt][ks], bz0, bz1);
            }
            // epilogue for rules 8j+2tig, 8j+2tig+1
#pragma unroll
            for (int mt = 0; mt < 2; mt++) {
                float w00 = exp2_fast(c1[mt][0] + c2[mt][0] + c3[mt][0]);
                float w01 = exp2_fast(c1[mt][1] + c2[mt][1] + c3[mt][1]);
                float w10 = exp2_fast(c1[mt][2] + c2[mt][2] + c3[mt][2]);
                float w11 = exp2_fast(c1[mt][3] + c2[mt][3] + c3[mt][3]);
                num[mt][0] = fmaf(cz[mt][0], w00, num[mt][0]);
                num[mt][0] = fmaf(cz[mt][1], w01, num[mt][0]);
                num[mt][1] = fmaf(cz[mt][2], w10, num[mt][1]);
                num[mt][1] = fmaf(cz[mt][3], w11, num[mt][1]);
                den[mt][0] += w00 + w01;
                den[mt][1] += w10 + w11;
            }
        }

        // ---- reduce across 4 tig lanes; tig==0 writes 4 rows ----
#pragma unroll
        for (int mt = 0; mt < 2; mt++)
#pragma unroll
            for (int rh = 0; rh < 2; rh++) {
                float n = num[mt][rh], d = den[mt][rh];
                n += __shfl_xor_sync(0xffffffffu, n, 1);
                d += __shfl_xor_sync(0xffffffffu, d, 1);
                n += __shfl_xor_sync(0xffffffffu, n, 2);
                d += __shfl_xor_sync(0xffffffffu, d, 2);
                if (tig == 0)
                    out[rowBase + mt * 16 + rh * 8 + g] = n / (d + 1e-13f);
            }
    }
}

extern "C" void kernel_launch(void* const* d_in, const int* in_sizes, int n_in,
                              void* d_out, int out_size) {
    const float* x = (const float*)d_in[0];      // [N, 16]
    const float* mu = (const float*)d_in[1];     // [64, 16]
    const float* sigma = (const float*)d_in[2];  // [64, 16]
    const float* rho = (const float*)d_in[3];    // [64, 17]
    float* out = (float*)d_out;                  // [N]

    fuzzy_mma_kernel<<<GRID, BLOCK>>>(x, mu, sigma, rho, out);
}